// round 17
// baseline (speedup 1.0000x reference)
#include <cuda_runtime.h>
#include <math.h>
#include <stdint.h>

#define OBS   128
#define PROJ  64
#define HID   256
#define LAT   24
#define BB    1024
#define TT    256
#define G3    768

// ---- device scratch --------------------------------------------------------
__device__ float g_gx [(size_t)BB * TT * G3];
__device__ float g_seq[(size_t)BB * TT * HID];      // mish(h) per (b,t)
__device__ float g_x  [(size_t)BB * TT * PROJ];     // x = obs@W_in + b_in
// W_hh bf16 b-frag order (rec): [q][gate p][(kc*8+w)*32+lane] uint4
__device__ uint4 g_Wmb[2 * 3 * 4096];
// W_ih tf32 b-frag order (preB): [(grp*8+kc)*32+lane] uint4, grp = w*6+ch
__device__ uint4 g_Wihm[48 * 8 * 32];

// ---- helpers ---------------------------------------------------------------
__device__ __forceinline__ void fma2(float2& d, float2 a, float2 b) {
    unsigned long long& dd = reinterpret_cast<unsigned long long&>(d);
    asm("fma.rn.f32x2 %0, %1, %2, %0;"
        : "+l"(dd)
        : "l"(reinterpret_cast<const unsigned long long&>(a)),
          "l"(reinterpret_cast<const unsigned long long&>(b)));
}
__device__ __forceinline__ float tanha(float x) {
    float y; asm("tanh.approx.f32 %0, %1;" : "=f"(y) : "f"(x)); return y;
}
__device__ __forceinline__ float siga(float x) {
    return fmaf(0.5f, tanha(0.5f * x), 0.5f);
}
__device__ __forceinline__ float mishf(float h) {
    float sp = __logf(1.f + __expf(h));
    return h * tanha(sp);
}
__device__ __forceinline__ uint32_t pkbf(float lo, float hi) {
    uint32_t r; asm("cvt.rn.bf16x2.f32 %0, %1, %2;" : "=r"(r) : "f"(hi), "f"(lo));
    return r;
}
__device__ __forceinline__ uint32_t to_tf32(float f) {
    uint32_t r; asm("cvt.rna.tf32.f32 %0, %1;" : "=r"(r) : "f"(f)); return r;
}

#define MMAB(cp, a0, a1, a2, a3, b0, b1)                                \
    asm("mma.sync.aligned.m16n8k16.row.col.f32.bf16.bf16.f32 "          \
        "{%0,%1,%2,%3}, {%4,%5,%6,%7}, {%8,%9}, {%0,%1,%2,%3};"         \
        : "+f"((cp)[0]), "+f"((cp)[1]), "+f"((cp)[2]), "+f"((cp)[3])    \
        : "r"(a0), "r"(a1), "r"(a2), "r"(a3), "r"(b0), "r"(b1))

#define MMAT(cp, a0, a1, a2, a3, b0, b1)                                \
    asm("mma.sync.aligned.m16n8k8.row.col.f32.tf32.tf32.f32 "           \
        "{%0,%1,%2,%3}, {%4,%5,%6,%7}, {%8,%9}, {%0,%1,%2,%3};"         \
        : "+f"((cp)[0]), "+f"((cp)[1]), "+f"((cp)[2]), "+f"((cp)[3])    \
        : "r"(a0), "r"(a1), "r"(a2), "r"(a3), "r"(b0), "r"(b1))

// ---- trm: W_hh -> bf16 b-frag order (unchanged, proven) --------------------
__global__ void trm_kernel(const float* __restrict__ W) {
    int gid = blockIdx.x * 256 + threadIdx.x;   // 24576
    if (gid >= 24576) return;
    int lane = gid & 31;
    int w  = (gid >> 5) & 7;
    int kc = (gid >> 8) & 15;
    int rest = gid >> 12;
    int p = rest % 3, q = rest / 3;
    int g = lane >> 2, tk = lane & 3;
    int k0 = kc * 16 + 2 * tk;
    uint4 v;
    #pragma unroll
    for (int half = 0; half < 2; half++) {
        int gcol = p * 256 + q * 128 + 16 * w + half * 8 + g;
        uint32_t b0 = pkbf(W[(size_t)k0 * G3 + gcol],
                           W[(size_t)(k0 + 1) * G3 + gcol]);
        uint32_t b1 = pkbf(W[(size_t)(k0 + 8) * G3 + gcol],
                           W[(size_t)(k0 + 9) * G3 + gcol]);
        if (half == 0) { v.x = b0; v.y = b1; } else { v.z = b0; v.w = b1; }
    }
    g_Wmb[(q * 3 + p) * 4096 + (kc * 8 + w) * 32 + lane] = v;
}

// ---- trmi: W_ih -> tf32 b-frag order for preB ------------------------------
__global__ void trmi_kernel(const float* __restrict__ W) {
    int gid = blockIdx.x * 256 + threadIdx.x;   // 12288
    if (gid >= 12288) return;
    int lane = gid & 31;
    int kc = (gid >> 5) & 7;
    int grp = gid >> 8;                 // 0..47
    int g = lane >> 2, tk = lane & 3;
    int n0 = grp * 16;
    uint4 v;
    v.x = to_tf32(W[(size_t)(kc * 8 + tk) * G3 + n0 + g]);
    v.y = to_tf32(W[(size_t)(kc * 8 + tk + 4) * G3 + n0 + g]);
    v.z = to_tf32(W[(size_t)(kc * 8 + tk) * G3 + n0 + 8 + g]);
    v.w = to_tf32(W[(size_t)(kc * 8 + tk + 4) * G3 + n0 + 8 + g]);
    g_Wihm[gid] = v;
}

// ---- preA: x = obs@W_in + b_in -> g_x (FFMA2, 32 rows/CTA) -----------------
__global__ __launch_bounds__(256) void preA_kernel(
    const float* __restrict__ obs, const float* __restrict__ W_in,
    const float* __restrict__ b_in)
{
    __shared__ float s_obsT[OBS][34];
    const int tid = threadIdx.x;
    const size_t row0 = (size_t)blockIdx.x * 32;

    for (int i = tid; i < 32 * OBS; i += 256) {
        int r = i >> 7, k = i & 127;
        s_obsT[k][r] = obs[(row0 + r) * OBS + k];
    }
    __syncthreads();

    const int p = tid & 63, rh = tid >> 6;
    const float bi = b_in[p];
    float2 acc[4];
    #pragma unroll
    for (int pr = 0; pr < 4; pr++) acc[pr] = make_float2(bi, bi);
    #pragma unroll 4
    for (int k = 0; k < OBS; k++) {
        float w = W_in[k * PROJ + p];
        float2 w2 = make_float2(w, w);
        #pragma unroll
        for (int pr = 0; pr < 4; pr++)
            fma2(acc[pr], w2, *(const float2*)&s_obsT[k][8 * rh + 2 * pr]);
    }
    #pragma unroll
    for (int pr = 0; pr < 4; pr++) {
        g_x[(row0 + 8 * rh + 2 * pr) * PROJ + p]     = acc[pr].x;
        g_x[(row0 + 8 * rh + 2 * pr + 1) * PROJ + p] = acc[pr].y;
    }
}

// ---- preB: gx = x@W_ih + b_ih via tf32 mma, 64 rows/CTA, 2 CTA/SM ----------
// warp w: cols 96w..96w+95 in 6 chunks of 16 (2 n8-tiles), 4 m-tiles.
// b-frags staged in two passes of 4 k-chunks (bb[4]) to hold regs <= 128.
#define XS 68
__global__ __launch_bounds__(256, 2) void preB_kernel(const float* __restrict__ b_ih)
{
    __shared__ float s_x[64 * XS];     // 17.4 KB

    const int tid  = threadIdx.x;
    const size_t row0 = (size_t)blockIdx.x * 64;
    const int w    = tid >> 5;
    const int lane = tid & 31;
    const int g    = lane >> 2;
    const int tk   = lane & 3;

    for (int i = tid; i < 64 * PROJ; i += 256) {
        int r = i >> 6, k = i & 63;
        s_x[r * XS + k] = g_x[(row0 + r) * PROJ + k];
    }
    __syncthreads();

    #pragma unroll 1
    for (int ch = 0; ch < 6; ch++) {
        const int n0 = 96 * w + 16 * ch;
        float2 bj0 = *(const float2*)&b_ih[n0 + 2 * tk];
        float2 bj1 = *(const float2*)&b_ih[n0 + 8 + 2 * tk];
        float acc[4][2][4];
        #pragma unroll
        for (int mt = 0; mt < 4; mt++) {
            acc[mt][0][0] = bj0.x; acc[mt][0][1] = bj0.y;
            acc[mt][0][2] = bj0.x; acc[mt][0][3] = bj0.y;
            acc[mt][1][0] = bj1.x; acc[mt][1][1] = bj1.y;
            acc[mt][1][2] = bj1.x; acc[mt][1][3] = bj1.y;
        }
        // two passes of 4 k-chunks; bb[4] keeps regs under the 128 cap
        #pragma unroll 1
        for (int half = 0; half < 2; half++) {
            uint4 bb[4];
            #pragma unroll
            for (int j = 0; j < 4; j++)
                bb[j] = g_Wihm[(((w * 6 + ch) * 8) + half * 4 + j) * 32 + lane];
            #pragma unroll
            for (int j = 0; j < 4; j++) {
                int kc = half * 4 + j;
                #pragma unroll
                for (int mt = 0; mt < 4; mt++) {
                    int base = (16 * mt + g) * XS + 8 * kc + tk;
                    uint32_t a0 = to_tf32(s_x[base]);
                    uint32_t a1 = to_tf32(s_x[base + 8 * XS]);
                    uint32_t a2 = to_tf32(s_x[base + 4]);
                    uint32_t a3 = to_tf32(s_x[base + 8 * XS + 4]);
                    MMAT(acc[mt][0], a0, a1, a2, a3, bb[j].x, bb[j].y);
                    MMAT(acc[mt][1], a0, a1, a2, a3, bb[j].z, bb[j].w);
                }
            }
        }
        #pragma unroll
        for (int mt = 0; mt < 4; mt++) {
            size_t r1 = row0 + 16 * mt + g;
            #pragma unroll
            for (int j = 0; j < 2; j++) {
                int c0 = n0 + 8 * j + 2 * tk;
                *(float2*)&g_gx[r1 * G3 + c0] =
                    make_float2(acc[mt][j][0], acc[mt][j][1]);
                *(float2*)&g_gx[(r1 + 8) * G3 + c0] =
                    make_float2(acc[mt][j][2], acc[mt][j][3]);
            }
        }
    }
}

// ---- rec: cluster-2 scan, bf16 mma, all weights in SMEM (proven) -----------
#define HBS   264
#define OFF_HB  196608
#define OFF_RST (OFF_HB + 2 * 16 * HBS * 2)
#define REC_SMEM (OFF_RST + 16 * TT)

__global__ __launch_bounds__(256, 1) __cluster_dims__(2, 1, 1)
void rec_kernel(const int* __restrict__ is_init, const float* __restrict__ hx,
                const float* __restrict__ b_hh, float* __restrict__ h_final)
{
    extern __shared__ char sm[];
    uint4* s_wb = (uint4*)sm;
    uint32_t* s_h32 = (uint32_t*)(sm + OFF_HB);
    unsigned char* s_rst = (unsigned char*)(sm + OFF_RST);

    const int tid  = threadIdx.x;
    const int q    = blockIdx.x & 1;
    const int b0c  = (blockIdx.x >> 1) * 16;
    const int w    = tid >> 5;
    const int lane = tid & 31;
    const int g    = lane >> 2;
    const int tk   = lane & 3;
    const int qb   = q * 128;

    {
        const uint4* src = g_Wmb + (size_t)q * 12288;
        for (int i = tid; i < 12288; i += 256) s_wb[i] = src[i];
    }
    for (int i = tid; i < 16 * TT; i += 256)
        s_rst[i] = (unsigned char)(is_init[(b0c + (i >> 8)) * TT + (i & 255)] != 0);
    for (int i = tid; i < 16 * 128; i += 256) {
        int r = i >> 7, kp = i & 127;
        bool m = (is_init[(b0c + r) * TT] != 0);
        float f0 = m ? 0.f : hx[(size_t)(b0c + r) * HID + 2 * kp];
        float f1 = m ? 0.f : hx[(size_t)(b0c + r) * HID + 2 * kp + 1];
        s_h32[r * 132 + kp] = pkbf(f0, f1);
    }

    const int brow[2] = { b0c + g, b0c + g + 8 };
    float bh[3][4];
    #pragma unroll
    for (int gate = 0; gate < 3; gate++)
        #pragma unroll
        for (int hf = 0; hf < 2; hf++) {
            int c0 = gate * 256 + qb + 16 * w + hf * 8 + 2 * tk;
            bh[gate][hf * 2]     = b_hh[c0];
            bh[gate][hf * 2 + 1] = b_hh[c0 + 1];
        }
    float hprev[2][4];
    #pragma unroll
    for (int rw = 0; rw < 2; rw++) {
        bool m = (is_init[brow[rw] * TT] != 0);
        #pragma unroll
        for (int hf = 0; hf < 2; hf++) {
            int u = 16 * w + hf * 8 + 2 * tk;
            hprev[rw][hf * 2]     = m ? 0.f : hx[(size_t)brow[rw] * HID + qb + u];
            hprev[rw][hf * 2 + 1] = m ? 0.f : hx[(size_t)brow[rw] * HID + qb + u + 1];
        }
    }

    __syncthreads();
    asm volatile("barrier.cluster.arrive.aligned;" ::: "memory");
    asm volatile("barrier.cluster.wait.aligned;" ::: "memory");

    uint32_t my_hb;
    asm("{ .reg .u64 t0; cvta.to.shared.u64 t0, %1; cvt.u32.u64 %0, t0; }"
        : "=r"(my_hb) : "l"(s_h32));
    uint32_t peer_hb;
    asm("mapa.shared::cluster.u32 %0, %1, %2;"
        : "=r"(peer_hb) : "r"(my_hb), "r"(q ^ 1));

    for (int t = 0; t < TT; t++) {
        const int rb = t & 1, wbuf = rb ^ 1;
        const int hbase = rb * 2112;

        float2 gxv[3][4];
        #pragma unroll
        for (int rw = 0; rw < 2; rw++) {
            const float* gp = g_gx + ((size_t)brow[rw] * TT + t) * G3 + qb + 16 * w;
            #pragma unroll
            for (int gate = 0; gate < 3; gate++) {
                gxv[gate][rw * 2]     = *(const float2*)(gp + gate * 256 + 2 * tk);
                gxv[gate][rw * 2 + 1] = *(const float2*)(gp + gate * 256 + 8 + 2 * tk);
            }
        }

        float accs[6][4];
        #pragma unroll
        for (int i = 0; i < 6; i++)
            #pragma unroll
            for (int e = 0; e < 4; e++) accs[i][e] = 0.f;

        #pragma unroll 4
        for (int kc = 0; kc < 16; kc++) {
            uint4 br = s_wb[(kc * 8 + w) * 32 + lane];
            uint4 bz = s_wb[4096 + (kc * 8 + w) * 32 + lane];
            uint4 bn = s_wb[8192 + (kc * 8 + w) * 32 + lane];
            uint32_t a0 = s_h32[hbase + g * 132 + kc * 8 + tk];
            uint32_t a1 = s_h32[hbase + (g + 8) * 132 + kc * 8 + tk];
            uint32_t a2 = s_h32[hbase + g * 132 + kc * 8 + tk + 4];
            uint32_t a3 = s_h32[hbase + (g + 8) * 132 + kc * 8 + tk + 4];
            MMAB(accs[0], a0, a1, a2, a3, br.x, br.y);
            MMAB(accs[1], a0, a1, a2, a3, br.z, br.w);
            MMAB(accs[2], a0, a1, a2, a3, bz.x, bz.y);
            MMAB(accs[3], a0, a1, a2, a3, bz.z, bz.w);
            MMAB(accs[4], a0, a1, a2, a3, bn.x, bn.y);
            MMAB(accs[5], a0, a1, a2, a3, bn.z, bn.w);
        }

        float hnew[2][4];
        #pragma unroll
        for (int rw = 0; rw < 2; rw++) {
            #pragma unroll
            for (int hf = 0; hf < 2; hf++) {
                float gxr0 = gxv[0][rw * 2 + hf].x, gxr1 = gxv[0][rw * 2 + hf].y;
                float gxz0 = gxv[1][rw * 2 + hf].x, gxz1 = gxv[1][rw * 2 + hf].y;
                float gxn0 = gxv[2][rw * 2 + hf].x, gxn1 = gxv[2][rw * 2 + hf].y;
                #pragma unroll
                for (int e = 0; e < 2; e++) {
                    int ce = hf * 2 + e;
                    int ai = rw * 2 + e;
                    float gxrv = e ? gxr1 : gxr0;
                    float gxzv = e ? gxz1 : gxz0;
                    float gxnv = e ? gxn1 : gxn0;
                    float rr = siga(gxrv + accs[0 + hf][ai] + bh[0][ce]);
                    float zz = siga(gxzv + accs[2 + hf][ai] + bh[1][ce]);
                    float nn = tanha(gxnv + rr * (accs[4 + hf][ai] + bh[2][ce]));
                    hnew[rw][ce] = nn + zz * (hprev[rw][ce] - nn);
                }
            }
        }

        if (t == TT - 1) {
            #pragma unroll
            for (int rw = 0; rw < 2; rw++)
                #pragma unroll
                for (int hf = 0; hf < 2; hf++) {
                    int u = qb + 16 * w + hf * 8 + 2 * tk;
                    *(float2*)&g_seq[((size_t)brow[rw] * TT + t) * HID + u] =
                        make_float2(mishf(hnew[rw][hf * 2]), mishf(hnew[rw][hf * 2 + 1]));
                    *(float2*)&h_final[(size_t)brow[rw] * HID + u] =
                        make_float2(hnew[rw][hf * 2], hnew[rw][hf * 2 + 1]);
                }
            break;
        }

        #pragma unroll
        for (int rw = 0; rw < 2; rw++) {
            int row = g + 8 * rw;
            bool mb = (s_rst[row * TT + t + 1] != 0);
            #pragma unroll
            for (int hf = 0; hf < 2; hf++) {
                float m0 = mb ? 0.f : hnew[rw][hf * 2];
                float m1 = mb ? 0.f : hnew[rw][hf * 2 + 1];
                uint32_t pk = pkbf(m0, m1);
                uint32_t idx = wbuf * 2112 + row * 132 + 64 * q + 8 * w + hf * 4 + tk;
                s_h32[idx] = pk;
                asm volatile("st.shared::cluster.b32 [%0], %1;"
                             :: "r"(peer_hb + idx * 4), "r"(pk) : "memory");
                hprev[rw][hf * 2]     = m0;
                hprev[rw][hf * 2 + 1] = m1;
            }
        }

        asm volatile("barrier.cluster.arrive.aligned;" ::: "memory");
        #pragma unroll
        for (int rw = 0; rw < 2; rw++)
            #pragma unroll
            for (int hf = 0; hf < 2; hf++) {
                int u = qb + 16 * w + hf * 8 + 2 * tk;
                *(float2*)&g_seq[((size_t)brow[rw] * TT + t) * HID + u] =
                    make_float2(mishf(hnew[rw][hf * 2]), mishf(hnew[rw][hf * 2 + 1]));
            }
        asm volatile("barrier.cluster.wait.aligned;" ::: "memory");
    }
}

// ---- post: out = g_seq @ W_out + b_out (mish precomputed in rec) -----------
__global__ __launch_bounds__(256) void post_kernel(
    const float* __restrict__ W_out, const float* __restrict__ b_out,
    float* __restrict__ out)
{
    __shared__ float s_m2[HID][32];
    __shared__ float s_w[HID * LAT];

    const int tid = threadIdx.x;
    const size_t row0 = (size_t)blockIdx.x * 32;

    for (int i = tid; i < HID * LAT; i += 256) s_w[i] = W_out[i];
    {
        const int row = tid & 31;
        const int kc  = (tid >> 5) * 32;
        const float* src = g_seq + (row0 + row) * HID + kc;
        #pragma unroll
        for (int c = 0; c < 8; c++) {
            float4 v = *(const float4*)(src + 4 * c);
            s_m2[kc + 4 * c + 0][row] = v.x;
            s_m2[kc + 4 * c + 1][row] = v.y;
            s_m2[kc + 4 * c + 2][row] = v.z;
            s_m2[kc + 4 * c + 3][row] = v.w;
        }
    }
    __syncthreads();

    if (tid < 192) {
        const int pg = tid / 24;
        const int l  = tid - pg * 24;
        float2 a0 = make_float2(0.f, 0.f), a1 = make_float2(0.f, 0.f);
        #pragma unroll 4
        for (int k = 0; k < HID; k++) {
            float4 m4 = *(const float4*)&s_m2[k][4 * pg];
            float w = s_w[k * LAT + l];
            float2 w2 = make_float2(w, w);
            fma2(a0, w2, make_float2(m4.x, m4.y));
            fma2(a1, w2, make_float2(m4.z, m4.w));
        }
        const float bl = b_out[l];
        out[(row0 + 4 * pg + 0) * LAT + l] = a0.x + bl;
        out[(row0 + 4 * pg + 1) * LAT + l] = a0.y + bl;
        out[(row0 + 4 * pg + 2) * LAT + l] = a1.x + bl;
        out[(row0 + 4 * pg + 3) * LAT + l] = a1.y + bl;
    }
}

// ---------------------------------------------------------------------------
extern "C" void kernel_launch(void* const* d_in, const int* in_sizes, int n_in,
                              void* d_out, int out_size) {
    const float* obs     = (const float*)d_in[0];
    const int*   is_init = (const int*)  d_in[1];
    const float* hx      = (const float*)d_in[2];
    const float* W_in    = (const float*)d_in[3];
    const float* b_in    = (const float*)d_in[4];
    const float* W_ih    = (const float*)d_in[5];
    const float* b_ih    = (const float*)d_in[6];
    const float* W_hh    = (const float*)d_in[7];
    const float* b_hh    = (const float*)d_in[8];
    const float* W_out   = (const float*)d_in[9];
    const float* b_out   = (const float*)d_in[10];

    float* out     = (float*)d_out;                 // [B,T,LAT]
    float* h_final = out + (size_t)BB * TT * LAT;   // [B,HID]

    cudaFuncSetAttribute(rec_kernel,
                         cudaFuncAttributeMaxDynamicSharedMemorySize, REC_SMEM);

    trm_kernel<<<96, 256>>>(W_hh);
    trmi_kernel<<<48, 256>>>(W_ih);
    preA_kernel<<<(BB * TT) / 32, 256>>>(obs, W_in, b_in);
    preB_kernel<<<(BB * TT) / 64, 256>>>(b_ih);
    rec_kernel<<<128, 256, REC_SMEM>>>(is_init, hx, b_hh, h_final);
    post_kernel<<<(BB * TT) / 32, 256>>>(W_out, b_out, out);
}